// round 17
// baseline (speedup 1.0000x reference)
#include <cuda_runtime.h>
#include <cuda_bf16.h>
#include <cstdint>

// Persistent 4-CTA-cluster LSTM scan, bf16 m16n8k16 HMMA, permuted-K layout,
// BULK DSMEM h exchange (R15), now with 512 threads / 16 warps:
// gate-pair split -> half the mma work per warp, 4 warps/SMSP.
// T=2048, B=256, E=128, H=256. 16 clusters x 4 CTAs = 64 CTAs.
// CTA rank r owns hidden units [64r,64r+64) -> 256 local gate rows = 32 nt
// (nt = g*8 + ub: gate g 0..3, unit block ub 0..7).
// Warp (half=wid>>3, wg=wid&7): ntA = 2*half*8+wg (gate 2*half),
//   ntB = ntA+8 (gate 2*half+1). half0 = gates i,f (+cell math, c resident);
//   half1 = gates g,o (publishes pre-activations via smem).
// Permuted per-CTA K (24 kt): kt0..3 own h (STS + bulk-copy source),
//   kt4..15 peer h (bulk copies in, parity mbarrier counts 3x2048 B),
//   kt16..23 x (staged locally).
// Step: wait -> post-wait mma 12 peer kt (W in 48 regs) -> stage x ->
//   half1 STS gate pre-acts -> sync -> half0 cell + STS own h -> sync ->
//   tid0: fence + 3x cp.async.bulk -> shadow mma (own-h + x, W smem).

#define T_STEPS 2048
#define BATCH   256
#define EDIM    128
#define HDIM    256
#define CLSZ    4
#define NTHR    512

// smem word map
#define WF_W        0        // W frags: 32nt x 12skt x 32 lanes uint2 = 24576 words
#define AF_W        24576    // A fragments: 2 buffers x 3072 words
#define AF_STRIDE_W 3072
#define XG_W        30720    // gate exchange: 8 x 256 floats = 2048 words
#define MB_W        32768    // 2 mbarriers, 8B each
#define SMEM_WORDS  32772    // 131088 bytes

#define AF_BYTE     (AF_W * 4)
#define MB_BYTE     (MB_W * 4)
#define AF_STRIDE_B (AF_STRIDE_W * 4)
#define OWN_BLK_B   2048                 // kt 0..3 = 4 kt x 512 B
#define TX_BYTES    (3 * OWN_BLK_B)      // 3 peers x 2048 B

extern __shared__ uint32_t smem_u[];

__device__ __forceinline__ uint32_t packbf(float lo, float hi) {
    uint32_t u;
    asm("cvt.rn.bf16x2.f32 %0, %1, %2;" : "=r"(u) : "f"(hi), "f"(lo));
    return u;
}
__device__ __forceinline__ float tanha(float x) {
    float y;
    asm("tanh.approx.f32 %0, %1;" : "=f"(y) : "f"(x));
    return y;
}
__device__ __forceinline__ float sigf(float x) { return fmaf(0.5f, tanha(0.5f * x), 0.5f); }
__device__ __forceinline__ void csync() {
    asm volatile("barrier.cluster.arrive.aligned;" ::: "memory");
    asm volatile("barrier.cluster.wait.aligned;" ::: "memory");
}
__device__ __forceinline__ uint32_t smem_u32(const void* p) {
    uint32_t a;
    asm("{ .reg .u64 t; cvta.to.shared.u64 t, %1; cvt.u32.u64 %0, t; }" : "=r"(a) : "l"(p));
    return a;
}
__device__ __forceinline__ uint32_t mapa32(uint32_t a, uint32_t r) {
    uint32_t d;
    asm("mapa.shared::cluster.u32 %0, %1, %2;" : "=r"(d) : "r"(a), "r"(r));
    return d;
}
__device__ __forceinline__ void mbar_init(uint32_t a, uint32_t n) {
    asm volatile("mbarrier.init.shared.b64 [%0], %1;" :: "r"(a), "r"(n) : "memory");
}
__device__ __forceinline__ void mbar_arm(uint32_t a, uint32_t tx) {
    asm volatile("mbarrier.arrive.expect_tx.shared.b64 _, [%0], %1;" :: "r"(a), "r"(tx) : "memory");
}
__device__ __forceinline__ void mbar_wait(uint32_t a, uint32_t phase) {
    uint32_t done;
    asm volatile(
        "{\n\t.reg .pred p;\n\t"
        "mbarrier.try_wait.parity.acquire.cluster.shared::cta.b64 p, [%1], %2;\n\t"
        "selp.b32 %0, 1, 0, p;\n\t}"
        : "=r"(done) : "r"(a), "r"(phase) : "memory");
    if (!done) {
        asm volatile(
            "{\n\t.reg .pred P1;\n\t"
            "W_%=:\n\t"
            "mbarrier.try_wait.parity.acquire.cluster.shared::cta.b64 P1, [%0], %1, 0x989680;\n\t"
            "@P1 bra.uni D_%=;\n\t"
            "bra.uni W_%=;\n\t"
            "D_%=:\n\t}"
            :: "r"(a), "r"(phase) : "memory");
    }
}
__device__ __forceinline__ void bulk_s2s(uint32_t dst, uint32_t src, uint32_t bytes,
                                         uint32_t mbar) {
    asm volatile(
        "cp.async.bulk.shared::cluster.shared::cta.mbarrier::complete_tx::bytes "
        "[%0], [%1], %2, [%3];"
        :: "r"(dst), "r"(src), "r"(bytes), "r"(mbar) : "memory");
}
__device__ __forceinline__ void fence_proxy_async_cta() {
    asm volatile("fence.proxy.async.shared::cta;" ::: "memory");
}
__device__ __forceinline__ void mma16816(float d[4], uint32_t a0, uint32_t a1, uint32_t a2,
                                         uint32_t a3, uint32_t b0, uint32_t b1) {
    asm volatile(
        "mma.sync.aligned.m16n8k16.row.col.f32.bf16.bf16.f32 "
        "{%0,%1,%2,%3},{%4,%5,%6,%7},{%8,%9},{%0,%1,%2,%3};"
        : "+f"(d[0]), "+f"(d[1]), "+f"(d[2]), "+f"(d[3])
        : "r"(a0), "r"(a1), "r"(a2), "r"(a3), "r"(b0), "r"(b1));
}
// word offset (within one A buffer) of packed pair holding A[row=b][col,col+1]
__device__ __forceinline__ int afrag_word(int b, int col) {
    int kt = col >> 4, kk = col & 15;
    int t3 = (kk >> 1) & 3;
    int r  = ((b >> 3) & 1) | (((kk >> 3) & 1) << 1);
    int ln = (b & 7) * 4 + t3;
    return (kt * 32 + ln) * 4 + r;
}

__global__ void __cluster_dims__(CLSZ, 1, 1) __launch_bounds__(NTHR, 1)
lstm_kernel(const int* __restrict__ inputs, const float* __restrict__ emb,
            const float* __restrict__ Wih, const float* __restrict__ Whh,
            const float* __restrict__ bih, const float* __restrict__ bhh,
            const float* __restrict__ Wout, const float* __restrict__ bout,
            float* __restrict__ out)
{
    const int tid  = threadIdx.x;
    const int lane = tid & 31;
    const int wid  = tid >> 5;
    const int wg   = wid & 7;          // unit-block column 0..7
    const int half = wid >> 3;         // 0: gates i,f ; 1: gates g,o
    const int gA   = 2 * half;         // first gate of this warp
    const int rank = blockIdx.x & (CLSZ - 1);
    const int cl   = blockIdx.x >> 2;

    uint2*    wf  = (uint2*)(smem_u + WF_W);
    uint32_t* af  = smem_u + AF_W;
    float*    xgb = (float*)(smem_u + XG_W);

    const uint32_t smem_base = smem_u32(smem_u);
    const uint32_t mbL       = smem_base + MB_BYTE;

    const int ntA = gA * 8 + wg;        // gate gA
    const int ntB = ntA + 8;            // gate gA+1

    // ---- one-time: smem W frags (skt 0..3 own-h, 4..11 x) ----
    for (int idx = tid; idx < 32 * 12 * 32; idx += NTHR) {
        int l   = idx & 31;
        int skt = (idx >> 5) % 12;
        int nt  = idx / (32 * 12);
        int n   = nt * 8 + (l >> 2);
        int R   = ((n >> 6) << 8) + rank * 64 + (n & 63);
        float w00, w01, w10, w11;
        if (skt < 4) {
            int ka = rank * 64 + skt * 16 + (l & 3) * 2;
            w00 = Whh[R * HDIM + ka];     w01 = Whh[R * HDIM + ka + 1];
            w10 = Whh[R * HDIM + ka + 8]; w11 = Whh[R * HDIM + ka + 8 + 1];
        } else {
            int ka = (skt - 4) * 16 + (l & 3) * 2;
            w00 = Wih[R * EDIM + ka];     w01 = Wih[R * EDIM + ka + 1];
            w10 = Wih[R * EDIM + ka + 8]; w11 = Wih[R * EDIM + ka + 8 + 1];
        }
        wf[idx] = make_uint2(packbf(w00, w01), packbf(w10, w11));
    }

    // ---- one-time: PEER h-part W (permuted kt 4..15) -> regs (48 regs) ----
    uint2 wregP[12], wregQ[12];
    {
        const int nbase = rank * 64 + wg * 8 + (lane >> 2);
        const int R_P = gA * 256 + nbase;
        const int R_Q = (gA + 1) * 256 + nbase;
        #pragma unroll
        for (int k = 0; k < 12; ++k) {
            int o  = (rank + 1 + (k >> 2)) & 3;
            int ka = o * 64 + (k & 3) * 16 + (lane & 3) * 2;
            wregP[k] = make_uint2(packbf(Whh[R_P * HDIM + ka],     Whh[R_P * HDIM + ka + 1]),
                                  packbf(Whh[R_P * HDIM + ka + 8], Whh[R_P * HDIM + ka + 8 + 1]));
            wregQ[k] = make_uint2(packbf(Whh[R_Q * HDIM + ka],     Whh[R_Q * HDIM + ka + 1]),
                                  packbf(Whh[R_Q * HDIM + ka + 8], Whh[R_Q * HDIM + ka + 8 + 1]));
        }
    }

    // ---- per-thread cell constants ----
    const int u0 = 8 * wg + ((lane & 3) << 1);
    const int b  = lane >> 2;
    float biasP0, biasP1, biasQ0, biasQ1;
    {
        int RP = gA * 256 + rank * 64 + u0;
        int RQ = (gA + 1) * 256 + rank * 64 + u0;
        biasP0 = bih[RP] + bhh[RP];       biasP1 = bih[RP + 1] + bhh[RP + 1];
        biasQ0 = bih[RQ] + bhh[RQ];       biasQ1 = bih[RQ + 1] + bhh[RQ + 1];
    }
    const int selfWord = afrag_word(b, u0);   // half0's local STS target
    const int xgIdx    = wg * 32 + lane;      // gate-exchange slot 0..255
    float cst[4] = {0.f, 0.f, 0.f, 0.f};      // used by half0 only

    // bulk-exchange targets (used by tid 0)
    uint32_t dstAF[3], dstMB[3];
    {
        int pi = 0;
        #pragma unroll
        for (int r = 0; r < CLSZ; ++r) {
            if (r == rank) continue;
            int q       = (rank - r - 1) & 3;
            uint32_t pb = mapa32(smem_base, (uint32_t)r);
            dstAF[pi]   = pb + AF_BYTE + (uint32_t)(4 + 4 * q) * 512u;
            dstMB[pi]   = pb + MB_BYTE;
            ++pi;
        }
    }

    // ---- staging constants: each thread stages 2 packed x words ----
    const int sb = tid >> 5;             // batch row 0..15
    const int sp = (lane) * 2;           // col-pair base (2 pairs per thread)
    int sword0 = afrag_word(sb, 256 + 2 * sp);
    int sword1 = afrag_word(sb, 256 + 2 * (sp + 1));

    // ---- mbarrier init + prologue ----
    if (tid == 0) {
        mbar_init(mbL + 0, 1);
        mbar_init(mbL + 8, 1);
        mbar_arm(mbL + 8, TX_BYTES);   // gen 1 -> mb1
    }
    for (int w = tid; w < 2 * AF_STRIDE_W; w += NTHR) af[w] = 0u;
    __syncthreads();
    {   // stage x(0) into buf0
        int tok = __ldg(&inputs[cl * 16 + sb]);
        float4 e = __ldg((const float4*)&emb[tok * EDIM + 2 * sp]);
        af[sword0] = packbf(e.x, e.y);
        af[sword1] = packbf(e.z, e.w);
    }
    __syncthreads();
    csync();   // barriers armed + buffers staged cluster-wide

    // ---- prime accumulators for step 0: bias + own-h(0)(=0) + x(0) ----
    float a1P[4], a1Q[4], a2P[4], a2Q[4];
    a1P[0] = biasP0; a1P[1] = biasP1; a1P[2] = biasP0; a1P[3] = biasP1;
    a1Q[0] = biasQ0; a1Q[1] = biasQ1; a1Q[2] = biasQ0; a1Q[3] = biasQ1;
    #pragma unroll
    for (int v = 0; v < 4; ++v) { a2P[v] = 0.f; a2Q[v] = 0.f; }
    #pragma unroll
    for (int skt = 0; skt < 12; ++skt) {
        int akt = (skt < 4) ? skt : (16 + skt - 4);
        uint4 a = *(const uint4*)(af + (akt * 32 + lane) * 4);
        uint2 bfP = wf[(ntA * 12 + skt) * 32 + lane];
        uint2 bfQ = wf[(ntB * 12 + skt) * 32 + lane];
        if (skt < 8) {
            mma16816(a1P, a.x, a.y, a.z, a.w, bfP.x, bfP.y);
            mma16816(a1Q, a.x, a.y, a.z, a.w, bfQ.x, bfQ.y);
        } else {
            mma16816(a2P, a.x, a.y, a.z, a.w, bfP.x, bfP.y);
            mma16816(a2Q, a.x, a.y, a.z, a.w, bfQ.x, bfQ.y);
        }
    }

    uint32_t ph0 = 0, ph1 = 0;

    #define STEP_BODY(T_, PAR_, MBOFF_, PHW_)                                              \
    {                                                                                      \
        const int t = (T_);                                                                \
        const uint32_t mbw = mbL + (MBOFF_);                                               \
        const uint32_t* cur = af + (PAR_) * AF_STRIDE_W;                                   \
        uint32_t*       nxt = af + (1 - (PAR_)) * AF_STRIDE_W;                             \
        const bool more = (t + 1 < T_STEPS);                                               \
        if (t > 0) { mbar_wait(mbw, PHW_); PHW_ ^= 1; }                                    \
        if (tid == 0) mbar_arm(mbw, TX_BYTES);                                             \
        float4 e;                                                                          \
        if (more) {                                                                        \
            int tok = __ldg(&inputs[(t + 1) * BATCH + cl * 16 + sb]);                      \
            e = __ldg((const float4*)&emb[tok * EDIM + 2 * sp]);                           \
        }                                                                                  \
        /* post-wait mma: 12 peer kt, W in regs; k0..5 -> a1, k6..11 -> a2 */              \
        _Pragma("unroll")                                                                  \
        for (int k = 0; k < 6; ++k) {                                                      \
            uint4 a = *(const uint4*)(cur + ((4 + k) * 32 + lane) * 4);                    \
            mma16816(a1P, a.x, a.y, a.z, a.w, wregP[k].x, wregP[k].y);                     \
            mma16816(a1Q, a.x, a.y, a.z, a.w, wregQ[k].x, wregQ[k].y);                     \
        }                                                                                  \
        _Pragma("unroll")                                                                  \
        for (int k = 6; k < 12; ++k) {                                                     \
            uint4 a = *(const uint4*)(cur + ((4 + k) * 32 + lane) * 4);                    \
            mma16816(a2P, a.x, a.y, a.z, a.w, wregP[k].x, wregP[k].y);                     \
            mma16816(a2Q, a.x, a.y, a.z, a.w, wregQ[k].x, wregQ[k].y);                     \
        }                                                                                  \
        /* stage x(t+1) */                                                                 \
        if (more) {                                                                        \
            nxt[sword0] = packbf(e.x, e.y);                                                \
            nxt[sword1] = packbf(e.z, e.w);                                                \
        }                                                                                  \
        /* half1 publishes gate pre-activations (g, o) */                                  \
        if (half == 1) {                                                                   \
            _Pragma("unroll")                                                              \
            for (int v = 0; v < 4; ++v) {                                                  \
                xgb[v * 256 + xgIdx]       = a1P[v] + a2P[v];   /* gate g */               \
                xgb[(4 + v) * 256 + xgIdx] = a1Q[v] + a2Q[v];   /* gate o */               \
            }                                                                              \
        }                                                                                  \
        __syncthreads();                                                                   \
        /* half0: cell math + own-h STS */                                                 \
        if (half == 0) {                                                                   \
            float i0 = sigf(a1P[0] + a2P[0]), i1 = sigf(a1P[1] + a2P[1]);                  \
            float i2 = sigf(a1P[2] + a2P[2]), i3 = sigf(a1P[3] + a2P[3]);                  \
            float f0 = sigf(a1Q[0] + a2Q[0]), f1 = sigf(a1Q[1] + a2Q[1]);                  \
            float f2 = sigf(a1Q[2] + a2Q[2]), f3 = sigf(a1Q[3] + a2Q[3]);                  \
            float g0 = tanha(xgb[0 * 256 + xgIdx]);                                        \
            float g1 = tanha(xgb[1 * 256 + xgIdx]);                                        \
            float g2 = tanha(xgb[2 * 256 + xgIdx]);                                        \
            float g3 = tanha(xgb[3 * 256 + xgIdx]);                                        \
            float o0 = sigf(xgb[4 * 256 + xgIdx]);                                         \
            float o1 = sigf(xgb[5 * 256 + xgIdx]);                                         \
            float o2 = sigf(xgb[6 * 256 + xgIdx]);                                         \
            float o3 = sigf(xgb[7 * 256 + xgIdx]);                                         \
            cst[0] = f0 * cst[0] + i0 * g0;                                                \
            cst[1] = f1 * cst[1] + i1 * g1;                                                \
            cst[2] = f2 * cst[2] + i2 * g2;                                                \
            cst[3] = f3 * cst[3] + i3 * g3;                                                \
            uint32_t hw0 = packbf(o0 * tanha(cst[0]), o1 * tanha(cst[1]));                 \
            uint32_t hw1 = packbf(o2 * tanha(cst[2]), o3 * tanha(cst[3]));                 \
            nxt[selfWord]     = hw0;                                                       \
            nxt[selfWord + 1] = hw1;                                                       \
        }                                                                                  \
        __syncthreads();   /* own-h(t+1) + x(t+1) complete before copy/shadow */           \
        if (tid == 0) {                                                                    \
            fence_proxy_async_cta();                                                       \
            uint32_t srcB = smem_base + AF_BYTE + (1 - (PAR_)) * AF_STRIDE_B;              \
            uint32_t dOff = (uint32_t)((1 - (PAR_)) * AF_STRIDE_B);                        \
            uint32_t mOff = (uint32_t)(8 - (MBOFF_));                                      \
            bulk_s2s(dstAF[0] + dOff, srcB, OWN_BLK_B, dstMB[0] + mOff);                   \
            bulk_s2s(dstAF[1] + dOff, srcB, OWN_BLK_B, dstMB[1] + mOff);                   \
            bulk_s2s(dstAF[2] + dOff, srcB, OWN_BLK_B, dstMB[2] + mOff);                   \
        }                                                                                  \
        /* SHADOW: accumulators for t+1 from local data (runs while copies fly) */         \
        a1P[0] = biasP0; a1P[1] = biasP1; a1P[2] = biasP0; a1P[3] = biasP1;                \
        a1Q[0] = biasQ0; a1Q[1] = biasQ1; a1Q[2] = biasQ0; a1Q[3] = biasQ1;                \
        _Pragma("unroll")                                                                  \
        for (int v = 0; v < 4; ++v) { a2P[v] = 0.f; a2Q[v] = 0.f; }                        \
        _Pragma("unroll")                                                                  \
        for (int skt = 0; skt < 4; ++skt) {   /* own-h kt 0..3 (always valid) */           \
            uint4 a = *(const uint4*)(nxt + (skt * 32 + lane) * 4);                        \
            uint2 bfP = wf[(ntA * 12 + skt) * 32 + lane];                                  \
            uint2 bfQ = wf[(ntB * 12 + skt) * 32 + lane];                                  \
            mma16816(a1P, a.x, a.y, a.z, a.w, bfP.x, bfP.y);                               \
            mma16816(a1Q, a.x, a.y, a.z, a.w, bfQ.x, bfQ.y);                               \
        }                                                                                  \
        if (more) {                           /* x kt 16..23 */                            \
            _Pragma("unroll")                                                              \
            for (int skt = 4; skt < 12; ++skt) {                                           \
                uint4 a = *(const uint4*)(nxt + ((16 + skt - 4) * 32 + lane) * 4);         \
                uint2 bfP = wf[(ntA * 12 + skt) * 32 + lane];                              \
                uint2 bfQ = wf[(ntB * 12 + skt) * 32 + lane];                              \
                if (skt < 8) {                                                             \
                    mma16816(a1P, a.x, a.y, a.z, a.w, bfP.x, bfP.y);                       \
                    mma16816(a1Q, a.x, a.y, a.z, a.w, bfQ.x, bfQ.y);                       \
                } else {                                                                   \
                    mma16816(a2P, a.x, a.y, a.z, a.w, bfP.x, bfP.y);                       \
                    mma16816(a2Q, a.x, a.y, a.z, a.w, bfQ.x, bfQ.y);                       \
                }                                                                          \
            }                                                                              \
        }                                                                                  \
    }

    for (int tt = 0; tt < T_STEPS; tt += 2) {
        STEP_BODY(tt,     0, 0, ph0)   // even: wait mb0, copies signal peers' mb1
        STEP_BODY(tt + 1, 1, 8, ph1)   // odd:  wait mb1, copies signal peers' mb0
    }
    #undef STEP_BODY

    // final: gen 2048 (parity at mb0) must land in every CTA before reads/exit
    mbar_wait(mbL + 0, ph0);

    // ---- head: h_T in buffer 0, PERMUTED fragment layout (rank 0's view) ----
    if (rank == 0 && tid < 16) {
        float s = __ldg(bout);
        int bb = tid;
        float accv = 0.0f;
        #pragma unroll 8
        for (int j = 0; j < HDIM; j += 2) {
            int o = j >> 6, w = j & 63;
            int kt = (o == 0) ? (w >> 4) : (4 + (o - 1) * 4 + (w >> 4));
            int colp = kt * 16 + (w & 15);
            uint32_t u = af[afrag_word(bb, colp)];
            float lo = __uint_as_float(u << 16);
            float hi = __uint_as_float(u & 0xFFFF0000u);
            accv += lo * __ldg(&Wout[j]) + hi * __ldg(&Wout[j + 1]);
        }
        out[cl * 16 + bb] = sigf(s + accv);
    }

    // keep cluster alive until all CTAs have received their final copies
    csync();
}

extern "C" void kernel_launch(void* const* d_in, const int* in_sizes, int n_in,
                              void* d_out, int out_size)
{
    (void)in_sizes; (void)n_in; (void)out_size;
    cudaFuncSetAttribute(lstm_kernel, cudaFuncAttributeMaxDynamicSharedMemorySize,
                         SMEM_WORDS * 4);
    lstm_kernel<<<16 * CLSZ, NTHR, SMEM_WORDS * 4>>>(
        (const int*)d_in[0], (const float*)d_in[1], (const float*)d_in[2],
        (const float*)d_in[3], (const float*)d_in[4], (const float*)d_in[5],
        (const float*)d_in[6], (const float*)d_in[7], (float*)d_out);
}